// round 2
// baseline (speedup 1.0000x reference)
#include <cuda_runtime.h>
#include <math.h>

#define BB 32
#define SS 1024
#define II 512
#define HH 512
#define GG 2048  // 4*H

// ---------------- device scratch (no mallocs allowed) ----------------
__device__ float g_xg[(size_t)SS * GG * BB];   // x-gates, layout [t][g][b], 256MB
__device__ float g_hbuf[2][HH * BB];           // h ping-pong, layout [j][b]
__device__ unsigned g_count = 0;               // grid barrier arrive counter (self-resetting)
__device__ unsigned g_gen   = 0;               // grid barrier generation (monotonic)

__device__ __forceinline__ unsigned ld_acq(const unsigned* p) {
    unsigned v;
    asm volatile("ld.acquire.gpu.u32 %0, [%1];" : "=r"(v) : "l"(p));
    return v;
}

// =====================================================================
// Kernel 1: xg[t][g][b] = sum_k x[b,t,k] * W_ih[g,k] + b_ih[g] + b_hh[g]
// Classic fp32 tiled GEMM: BM=BN=128, BK=16, 256 threads, 8x8 per thread.
// =====================================================================
__global__ void __launch_bounds__(256) xgates_gemm(
    const float* __restrict__ x, const float* __restrict__ Wih,
    const float* __restrict__ bih, const float* __restrict__ bhh)
{
    __shared__ float As[16 * 132];  // transposed A tile, padded pitch 132 (conflict-free)
    __shared__ float Bs[16 * 132];

    const int tid = threadIdx.x;
    const int tx = tid & 15, ty = tid >> 4;
    const int m0 = blockIdx.y * 128;   // m = b*S + t
    const int n0 = blockIdx.x * 128;   // n = gate row g

    float acc[8][8];
#pragma unroll
    for (int i = 0; i < 8; i++)
#pragma unroll
        for (int j = 0; j < 8; j++) acc[i][j] = 0.f;

    for (int k0 = 0; k0 < II; k0 += 16) {
#pragma unroll
        for (int s = 0; s < 2; s++) {
            int li = tid + s * 256;          // 0..511 float4 slots
            int mr = li >> 2;                // 0..127
            int kc = (li & 3) << 2;          // 0,4,8,12
            float4 va = *(const float4*)&x[(size_t)(m0 + mr) * II + k0 + kc];
            As[(kc + 0) * 132 + mr] = va.x;
            As[(kc + 1) * 132 + mr] = va.y;
            As[(kc + 2) * 132 + mr] = va.z;
            As[(kc + 3) * 132 + mr] = va.w;
            float4 vb = *(const float4*)&Wih[(size_t)(n0 + mr) * II + k0 + kc];
            Bs[(kc + 0) * 132 + mr] = vb.x;
            Bs[(kc + 1) * 132 + mr] = vb.y;
            Bs[(kc + 2) * 132 + mr] = vb.z;
            Bs[(kc + 3) * 132 + mr] = vb.w;
        }
        __syncthreads();
#pragma unroll
        for (int kk = 0; kk < 16; kk++) {
            float a[8], bf[8];
            *(float4*)&a[0]  = *(const float4*)&As[kk * 132 + ty * 8];
            *(float4*)&a[4]  = *(const float4*)&As[kk * 132 + ty * 8 + 4];
            *(float4*)&bf[0] = *(const float4*)&Bs[kk * 132 + tx * 8];
            *(float4*)&bf[4] = *(const float4*)&Bs[kk * 132 + tx * 8 + 4];
#pragma unroll
            for (int i = 0; i < 8; i++)
#pragma unroll
                for (int j = 0; j < 8; j++) acc[i][j] += a[i] * bf[j];
        }
        __syncthreads();
    }

    // epilogue: add biases, store transposed to [t][g][b]
    float bias[8];
#pragma unroll
    for (int j = 0; j < 8; j++) {
        int n = n0 + tx * 8 + j;
        bias[j] = bih[n] + bhh[n];
    }
#pragma unroll
    for (int i = 0; i < 8; i++) {
        int m = m0 + ty * 8 + i;
        int b = m >> 10;       // S = 1024
        int t = m & 1023;
#pragma unroll
        for (int j = 0; j < 8; j++) {
            int n = n0 + tx * 8 + j;
            g_xg[((size_t)t * GG + n) * BB + b] = acc[i][j] + bias[j];
        }
    }
}

// =====================================================================
// Kernel 2: persistent recurrence. 128 CTAs x 256 threads.
// CTA r owns h-indices j0..j0+3 (16 gate rows: 4 types x 4 j).
// W slice (16x512) persists in SMEM; h lives in registers (k split over
// 8 warps, 64 values/lane); grid-wide barrier per step.
// =====================================================================
__global__ void __launch_bounds__(256) lstm_rec(
    const float* __restrict__ Whh, const float* __restrict__ h0,
    const float* __restrict__ c0, float* __restrict__ out, int write_hc)
{
    extern __shared__ float sm[];
    float* Ws   = sm;           // 16*512 floats = 32KB
    float* part = sm + 16 * 512; // 16*8*32 floats = 16KB

    const int tid  = threadIdx.x;
    const int w    = tid >> 5;   // warp 0..7 -> k chunk of 64
    const int lane = tid & 31;   // lane = batch index
    const int j0   = blockIdx.x * 4;

    // ---- load this CTA's 16 W_hh rows into SMEM (once) ----
#pragma unroll
    for (int s = 0; s < 8; s++) {
        int idx = tid + s * 256;        // float4 slot, 0..2047
        int rr  = idx >> 7;             // 128 float4 per row
        int k4  = (idx & 127) << 2;
        int g   = (rr >> 2) * 512 + j0 + (rr & 3);   // rr = type*4 + jj
        *(float4*)&Ws[rr * 512 + k4] = *(const float4*)&Whh[(size_t)g * HH + k4];
    }

    // ---- init c (register of reduce thread) and h buffer 0 ----
    float creg = 0.f;
    if (tid < 128) {
        int jj = tid >> 5;
        int b  = tid & 31;
        creg = c0[(size_t)b * HH + j0 + jj];
        g_hbuf[0][(j0 + jj) * BB + b] = h0[(size_t)b * HH + j0 + jj];
    }

    unsigned my_gen = 0;
    if (tid == 0) my_gen = ld_acq(&g_gen);

    const unsigned nb = gridDim.x;

    // initial grid barrier: h buffer 0 visible everywhere
    __syncthreads();
    if (tid == 0) {
        __threadfence();
        if (atomicAdd(&g_count, 1u) == nb - 1u) {
            g_count = 0;
            __threadfence();
            atomicExch(&g_gen, my_gen + 1u);
            my_gen = my_gen + 1u;
        } else {
            unsigned v;
            do { __nanosleep(20); v = ld_acq(&g_gen); } while (v == my_gen);
            my_gen = v;
        }
    }
    __syncthreads();

#pragma unroll 1
    for (int t = 0; t < SS; t++) {
        const float* cur = g_hbuf[t & 1];
        float*       nxt = g_hbuf[(t + 1) & 1];

        // ---- load h chunk (64 k's for this warp) into registers, bypass L1 ----
        float hreg[64];
#pragma unroll
        for (int i = 0; i < 64; i++)
            hreg[i] = __ldcg(&cur[(w * 64 + i) * BB + lane]);

        // ---- 16 partial dot products (this warp's k chunk) ----
        float acc[16];
#pragma unroll
        for (int rr = 0; rr < 16; rr++) acc[rr] = 0.f;
#pragma unroll
        for (int i4 = 0; i4 < 16; i4++) {
#pragma unroll
            for (int rr = 0; rr < 16; rr++) {
                float4 wv = *(const float4*)&Ws[rr * 512 + w * 64 + i4 * 4];
                acc[rr] += wv.x * hreg[i4 * 4 + 0] + wv.y * hreg[i4 * 4 + 1]
                         + wv.z * hreg[i4 * 4 + 2] + wv.w * hreg[i4 * 4 + 3];
            }
        }
#pragma unroll
        for (int rr = 0; rr < 16; rr++)
            part[rr * 256 + w * 32 + lane] = acc[rr];
        __syncthreads();

        // ---- reduce across warps + nonlinearity (threads 0..127) ----
        if (tid < 128) {
            int jj = tid >> 5;
            int b  = tid & 31;
            float gate[4];
#pragma unroll
            for (int tt = 0; tt < 4; tt++) {
                int rr = tt * 4 + jj;
                float s = __ldg(&g_xg[((size_t)t * GG + tt * 512 + j0 + jj) * BB + b]);
#pragma unroll
                for (int ww = 0; ww < 8; ww++) s += part[rr * 256 + ww * 32 + b];
                gate[tt] = s;
            }
            float ig = 1.f / (1.f + expf(-gate[0]));
            float fg = 1.f / (1.f + expf(-gate[1]));
            float gg = tanhf(gate[2]);
            float og = 1.f / (1.f + expf(-gate[3]));
            float c  = fg * creg + ig * gg;
            creg = c;
            float h  = og * tanhf(c);
            __stcg(&nxt[(j0 + jj) * BB + b], h);
            out[((size_t)b * SS + t) * HH + j0 + jj] = h;
            if (t == SS - 1 && write_hc) {
                size_t base = (size_t)BB * SS * HH;
                out[base + (size_t)b * HH + j0 + jj] = h;                       // h_n
                out[base + (size_t)BB * HH + (size_t)b * HH + j0 + jj] = c;     // c_n
            }
        }

        // ---- grid barrier ----
        __syncthreads();
        if (tid == 0) {
            __threadfence();
            if (atomicAdd(&g_count, 1u) == nb - 1u) {
                g_count = 0;
                __threadfence();
                atomicExch(&g_gen, my_gen + 1u);
                my_gen = my_gen + 1u;
            } else {
                unsigned v;
                do { __nanosleep(20); v = ld_acq(&g_gen); } while (v == my_gen);
                my_gen = v;
            }
        }
        __syncthreads();
    }
}

// =====================================================================
extern "C" void kernel_launch(void* const* d_in, const int* in_sizes, int n_in,
                              void* d_out, int out_size)
{
    const float* x   = (const float*)d_in[0];
    const float* Wih = (const float*)d_in[1];
    const float* Whh = (const float*)d_in[2];
    const float* bih = (const float*)d_in[3];
    const float* bhh = (const float*)d_in[4];
    const float* h0  = (const float*)d_in[5];
    const float* c0  = (const float*)d_in[6];
    float* out = (float*)d_out;

    // only write h_n / c_n tails if the output buffer includes them
    long long need = (long long)BB * SS * HH + 2LL * BB * HH;
    int write_hc = ((long long)out_size >= need) ? 1 : 0;

    int smem = (16 * 512 + 16 * 8 * 32) * (int)sizeof(float);  // 48KB
    cudaFuncSetAttribute(lstm_rec, cudaFuncAttributeMaxDynamicSharedMemorySize, smem);

    dim3 ggrid(GG / 128, (BB * SS) / 128);  // (16, 256)
    xgates_gemm<<<ggrid, 256>>>(x, Wih, bih, bhh);
    lstm_rec<<<128, 256, smem>>>(Whh, h0, c0, out, write_hc);
}

// round 3
// speedup vs baseline: 1.1309x; 1.1309x over previous
#include <cuda_runtime.h>
#include <math.h>

#define BB 32
#define SS 1024
#define II 512
#define HH 512
#define GG 2048  // 4*H

typedef unsigned long long u64;

// ---------------- device scratch (no mallocs allowed) ----------------
__device__ float g_xg[(size_t)SS * GG * BB];    // x-gates, layout [t][g][b]
__device__ float g_hbuf[2][HH * BB];            // h ping-pong, pair layout [k/2][b][2]
__device__ unsigned g_count = 0;
__device__ unsigned g_gen   = 0;

__device__ __forceinline__ unsigned ld_acq(const unsigned* p) {
    unsigned v;
    asm volatile("ld.acquire.gpu.u32 %0, [%1];" : "=r"(v) : "l"(p));
    return v;
}
__device__ __forceinline__ u64 fma2(u64 a, u64 b, u64 c) {
    u64 d;
    asm("fma.rn.f32x2 %0, %1, %2, %3;" : "=l"(d) : "l"(a), "l"(b), "l"(c));
    return d;
}
__device__ __forceinline__ u64 pack2(float x, float y) {
    u64 r;
    asm("mov.b64 %0, {%1, %2};" : "=l"(r) : "r"(__float_as_uint(x)), "r"(__float_as_uint(y)));
    return r;
}
__device__ __forceinline__ float2 unpack2(u64 v) {
    unsigned lo, hi;
    asm("mov.b64 {%0, %1}, %2;" : "=r"(lo), "=r"(hi) : "l"(v));
    return make_float2(__uint_as_float(lo), __uint_as_float(hi));
}

// =====================================================================
// Kernel 1: xg[t][g][b] = sum_k x[b,t,k]*W_ih[g,k] + b_ih[g] + b_hh[g]
// 128x128x16 fp32 tile, 256 thr, 8x8/thread, inner product via FFMA2.
// =====================================================================
__global__ void __launch_bounds__(256) xgates_gemm(
    const float* __restrict__ x, const float* __restrict__ Wih,
    const float* __restrict__ bih, const float* __restrict__ bhh)
{
    __shared__ float As[16 * 132];
    __shared__ float Bs[16 * 132];

    const int tid = threadIdx.x;
    const int tx = tid & 15, ty = tid >> 4;
    const int m0 = blockIdx.y * 128;
    const int n0 = blockIdx.x * 128;

    u64 acc2[8][4];
#pragma unroll
    for (int i = 0; i < 8; i++)
#pragma unroll
        for (int j = 0; j < 4; j++) acc2[i][j] = 0ull;

    for (int k0 = 0; k0 < II; k0 += 16) {
#pragma unroll
        for (int s = 0; s < 2; s++) {
            int li = tid + s * 256;
            int mr = li >> 2;
            int kc = (li & 3) << 2;
            float4 va = *(const float4*)&x[(size_t)(m0 + mr) * II + k0 + kc];
            As[(kc + 0) * 132 + mr] = va.x;
            As[(kc + 1) * 132 + mr] = va.y;
            As[(kc + 2) * 132 + mr] = va.z;
            As[(kc + 3) * 132 + mr] = va.w;
            float4 vb = *(const float4*)&Wih[(size_t)(n0 + mr) * II + k0 + kc];
            Bs[(kc + 0) * 132 + mr] = vb.x;
            Bs[(kc + 1) * 132 + mr] = vb.y;
            Bs[(kc + 2) * 132 + mr] = vb.z;
            Bs[(kc + 3) * 132 + mr] = vb.w;
        }
        __syncthreads();
#pragma unroll
        for (int kk = 0; kk < 16; kk++) {
            float a[8];
            *(float4*)&a[0] = *(const float4*)&As[kk * 132 + ty * 8];
            *(float4*)&a[4] = *(const float4*)&As[kk * 132 + ty * 8 + 4];
            // 8 j-values as 4 packed pairs (reinterpret: float pair == f32x2)
            ulonglong2 b01 = *(const ulonglong2*)&Bs[kk * 132 + tx * 8];
            ulonglong2 b23 = *(const ulonglong2*)&Bs[kk * 132 + tx * 8 + 4];
#pragma unroll
            for (int i = 0; i < 8; i++) {
                u64 ad = pack2(a[i], a[i]);
                acc2[i][0] = fma2(ad, b01.x, acc2[i][0]);
                acc2[i][1] = fma2(ad, b01.y, acc2[i][1]);
                acc2[i][2] = fma2(ad, b23.x, acc2[i][2]);
                acc2[i][3] = fma2(ad, b23.y, acc2[i][3]);
            }
        }
        __syncthreads();
    }

    float bias[8];
#pragma unroll
    for (int j = 0; j < 8; j++) {
        int n = n0 + tx * 8 + j;
        bias[j] = bih[n] + bhh[n];
    }
#pragma unroll
    for (int i = 0; i < 8; i++) {
        int m = m0 + ty * 8 + i;
        int b = m >> 10;
        int t = m & 1023;
#pragma unroll
        for (int j2 = 0; j2 < 4; j2++) {
            float2 v = unpack2(acc2[i][j2]);
            int n = n0 + tx * 8 + j2 * 2;
            g_xg[((size_t)t * GG + n + 0) * BB + b] = v.x + bias[j2 * 2 + 0];
            g_xg[((size_t)t * GG + n + 1) * BB + b] = v.y + bias[j2 * 2 + 1];
        }
    }
}

// =====================================================================
// Kernel 2: persistent recurrence. 128 CTAs x 256 thr, CTA owns 4 h-idx
// (16 gate rows). W slice in SMEM; h in regs as k-pairs; FFMA2 mainloop;
// release/acquire grid barrier per step.
// =====================================================================
__global__ void __launch_bounds__(256) lstm_rec(
    const float* __restrict__ Whh, const float* __restrict__ h0,
    const float* __restrict__ c0, float* __restrict__ out, int write_hc)
{
    extern __shared__ float sm[];
    float* Ws   = sm;            // 16*512 floats = 32KB
    float* part = sm + 16 * 512; // 16*256 floats = 16KB

    const int tid  = threadIdx.x;
    const int w    = tid >> 5;
    const int lane = tid & 31;
    const int j0   = blockIdx.x * 4;

    // ---- W_hh slice (16 rows x 512) -> SMEM, once ----
#pragma unroll
    for (int s = 0; s < 8; s++) {
        int idx = tid + s * 256;
        int rr  = idx >> 7;
        int k4  = (idx & 127) << 2;
        int g   = (rr >> 2) * 512 + j0 + (rr & 3);
        *(float4*)&Ws[rr * 512 + k4] = *(const float4*)&Whh[(size_t)g * HH + k4];
    }

    // ---- init c and h buffer 0 (pair layout: elem (k>>1)*64 + b*2 + (k&1)) ----
    float creg = 0.f;
    if (tid < 128) {
        int jj = tid >> 5;
        int b  = tid & 31;
        int j  = j0 + jj;
        creg = c0[(size_t)b * HH + j];
        g_hbuf[0][(j >> 1) * 64 + b * 2 + (j & 1)] = h0[(size_t)b * HH + j];
    }

    unsigned my_gen = 0;
    if (tid == 0) my_gen = ld_acq(&g_gen);
    const unsigned nb = gridDim.x;

    // initial grid barrier
    __syncthreads();
    if (tid == 0) {
        unsigned old;
        asm volatile("atom.release.gpu.global.add.u32 %0, [%1], %2;"
                     : "=r"(old) : "l"(&g_count), "r"(1u));
        if (old == nb - 1u) {
            g_count = 0;
            asm volatile("atom.release.gpu.global.exch.b32 %0, [%1], %2;"
                         : "=r"(old) : "l"(&g_gen), "r"(my_gen + 1u));
            my_gen += 1u;
        } else {
            unsigned v;
            do { v = ld_acq(&g_gen); } while (v == my_gen);
            my_gen = v;
        }
    }
    __syncthreads();

#pragma unroll 1
    for (int t = 0; t < SS; t++) {
        const u64* cur = (const u64*)g_hbuf[t & 1];
        float*     nxt = g_hbuf[(t + 1) & 1];

        // ---- prefetch x-gates for the reduce phase (off critical path) ----
        float xpre[4];
        if (tid < 128) {
            int jj = tid >> 5;
            int b  = tid & 31;
#pragma unroll
            for (int tt = 0; tt < 4; tt++)
                xpre[tt] = __ldg(&g_xg[((size_t)t * GG + tt * 512 + j0 + jj) * BB + b]);
        }

        // ---- load this warp's 32 h k-pairs (coalesced LDG.64, L1 bypass) ----
        u64 h2[32];
#pragma unroll
        for (int i = 0; i < 32; i++)
            h2[i] = __ldcg(&cur[(w * 32 + i) * 32 + lane]);

        // ---- 16 partial dots via FFMA2, two acc banks to break RAW ----
        u64 acc_a[16], acc_b[16];
#pragma unroll
        for (int rr = 0; rr < 16; rr++) { acc_a[rr] = 0ull; acc_b[rr] = 0ull; }
#pragma unroll
        for (int q = 0; q < 16; q++) {          // q covers 4 k (2 pairs)
#pragma unroll
            for (int rr = 0; rr < 16; rr++) {
                ulonglong2 wv = *(const ulonglong2*)&Ws[rr * 512 + w * 64 + q * 4];
                acc_a[rr] = fma2(wv.x, h2[q * 2 + 0], acc_a[rr]);
                acc_b[rr] = fma2(wv.y, h2[q * 2 + 1], acc_b[rr]);
            }
        }
#pragma unroll
        for (int rr = 0; rr < 16; rr++) {
            float2 va = unpack2(acc_a[rr]);
            float2 vb = unpack2(acc_b[rr]);
            part[rr * 256 + w * 32 + lane] = (va.x + va.y) + (vb.x + vb.y);
        }
        __syncthreads();

        // ---- reduce + nonlinearity (threads 0..127) ----
        if (tid < 128) {
            int jj = tid >> 5;
            int b  = tid & 31;
            int j  = j0 + jj;
            float gate[4];
#pragma unroll
            for (int tt = 0; tt < 4; tt++) {
                int rr = tt * 4 + jj;
                float s = xpre[tt];
#pragma unroll
                for (int ww = 0; ww < 8; ww++) s += part[rr * 256 + ww * 32 + b];
                gate[tt] = s;
            }
            float ig = 1.f / (1.f + expf(-gate[0]));
            float fg = 1.f / (1.f + expf(-gate[1]));
            float gg = tanhf(gate[2]);
            float og = 1.f / (1.f + expf(-gate[3]));
            float c  = fg * creg + ig * gg;
            creg = c;
            float h  = og * tanhf(c);
            __stcg(&nxt[(j >> 1) * 64 + b * 2 + (j & 1)], h);
            out[((size_t)b * SS + t) * HH + j] = h;
            if (t == SS - 1 && write_hc) {
                size_t base = (size_t)BB * SS * HH;
                out[base + (size_t)b * HH + j] = h;
                out[base + (size_t)BB * HH + (size_t)b * HH + j] = c;
            }
        }

        // ---- grid barrier (release/acquire, no membar) ----
        __syncthreads();
        if (tid == 0) {
            unsigned old;
            asm volatile("atom.release.gpu.global.add.u32 %0, [%1], %2;"
                         : "=r"(old) : "l"(&g_count), "r"(1u));
            if (old == nb - 1u) {
                g_count = 0;
                asm volatile("atom.release.gpu.global.exch.b32 %0, [%1], %2;"
                             : "=r"(old) : "l"(&g_gen), "r"(my_gen + 1u));
                my_gen += 1u;
            } else {
                unsigned v;
                do { v = ld_acq(&g_gen); } while (v == my_gen);
                my_gen = v;
            }
        }
        __syncthreads();
    }
}

// =====================================================================
extern "C" void kernel_launch(void* const* d_in, const int* in_sizes, int n_in,
                              void* d_out, int out_size)
{
    const float* x   = (const float*)d_in[0];
    const float* Wih = (const float*)d_in[1];
    const float* Whh = (const float*)d_in[2];
    const float* bih = (const float*)d_in[3];
    const float* bhh = (const float*)d_in[4];
    const float* h0  = (const float*)d_in[5];
    const float* c0  = (const float*)d_in[6];
    float* out = (float*)d_out;

    long long need = (long long)BB * SS * HH + 2LL * BB * HH;
    int write_hc = ((long long)out_size >= need) ? 1 : 0;

    int smem = (16 * 512 + 16 * 256) * (int)sizeof(float);  // 48KB
    cudaFuncSetAttribute(lstm_rec, cudaFuncAttributeMaxDynamicSharedMemorySize, smem);

    dim3 ggrid(GG / 128, (BB * SS) / 128);
    xgates_gemm<<<ggrid, 256>>>(x, Wih, bih, bhh);
    lstm_rec<<<128, 256, smem>>>(Whh, h0, c0, out, write_hc);
}